// round 5
// baseline (speedup 1.0000x reference)
#include <cuda_runtime.h>
#include <cstdint>
#include <math.h>

#define BATCH 8192
#define PLANE (8192 * 128)
#define GAIN 1.5927116870880127f
#define INV_SQRT3 0.57735026918962576f

// ---------------------------------------------------------------------------
// Scratch (device globals; no allocation in kernel_launch)
// ---------------------------------------------------------------------------
__device__ float g_s [PLANE];
__device__ float g_v [3 * PLANE];
__device__ float g_s1[PLANE];
__device__ float g_v1[3 * PLANE];
__device__ float g_s2[PLANE];
__device__ float g_v2[3 * PLANE];
__device__ float g_ts[PLANE];
__device__ float g_tv[3 * PLANE];
// packed bf16 hi/lo weights (prepass output)
__device__ uint32_t g_wp2[4u * 128 * 128 * 128];   // block2: 4 planes
__device__ uint32_t g_wp1[4u * 64 * 64 * 128];     // block1: 4 planes

// ---------------------------------------------------------------------------
// helpers (non-arch-gated PTX only: mma.sync bf16 m16n8k16 + cp.async, sm80+)
// ---------------------------------------------------------------------------
__device__ __forceinline__ uint32_t smem_u32(const void* p) {
    uint32_t a;
    asm("{ .reg .u64 t; cvta.to.shared.u64 t, %1; cvt.u32.u64 %0, t; }" : "=r"(a) : "l"(p));
    return a;
}
#define MMA_BF16(d, a0, a1, a2, a3, b0, b1)                                 \
    asm volatile(                                                           \
        "mma.sync.aligned.m16n8k16.row.col.f32.bf16.bf16.f32 "              \
        "{%0,%1,%2,%3}, {%4,%5,%6,%7}, {%8,%9}, {%0,%1,%2,%3};"             \
        : "+f"((d)[0]), "+f"((d)[1]), "+f"((d)[2]), "+f"((d)[3])            \
        : "r"(a0), "r"(a1), "r"(a2), "r"(a3), "r"(b0), "r"(b1))

#define CP_ASYNC16(sa, gp) \
    asm volatile("cp.async.ca.shared.global [%0], [%1], 16;" :: "r"(sa), "l"(gp) : "memory")
#define CP_COMMIT() asm volatile("cp.async.commit_group;" ::: "memory")
#define CP_WAIT1()  asm volatile("cp.async.wait_group 1;" ::: "memory")
#define CP_WAIT0()  asm volatile("cp.async.wait_group 0;" ::: "memory")

// split x0,x1 into packed bf16 hi word and lo (residual) word; low half = x0
__device__ __forceinline__ void split_pack(float x0, float x1,
                                           uint32_t& hi, uint32_t& lo) {
    uint32_t h;
    asm("cvt.rn.bf16x2.f32 %0, %1, %2;" : "=r"(h) : "f"(x1), "f"(x0));
    float h0 = __uint_as_float(h << 16);
    float h1 = __uint_as_float(h & 0xFFFF0000u);
    float l0 = x0 - h0;
    float l1 = x1 - h1;
    asm("cvt.rn.bf16x2.f32 %0, %1, %2;" : "=r"(lo) : "f"(l1), "f"(l0));
    hi = h;
}

// ---------------------------------------------------------------------------
// Weight prepass: fp32 w[u*M+v][n] -> packed hi/lo bf16x2 words, layout:
// block = vw*M + u (2048 words):
//   [hilo][kp 0..7][n' 0..127], n' = (n&7)*16 + (n>>3),
//   word = bf16(w[v=vw*16+2kp][n]) | bf16(w[v+1][n])<<16
// ---------------------------------------------------------------------------
__global__ void pack_weights_kernel(const float* __restrict__ w,
                                    uint32_t* __restrict__ dst, int M) {
    int idx = blockIdx.x * 256 + threadIdx.x;
    int total = (M * M / 2) * 128;
    if (idx >= total) return;
    int kpair = idx >> 7, n = idx & 127;
    int u = kpair / (M / 2), rem = kpair % (M / 2);
    int vw = rem >> 3, kp = rem & 7;
    int v = vw * 16 + 2 * kp;
    float x0 = w[((size_t)u * M + v) * 128 + n];
    float x1 = w[((size_t)u * M + v + 1) * 128 + n];
    uint32_t hi, lo;
    split_pack(x0, x1, hi, lo);
    int np = (n & 7) * 16 + (n >> 3);
    size_t base = ((size_t)(vw * M + u)) * 2048;
    dst[base + kp * 128 + np] = hi;
    dst[base + 1024 + kp * 128 + np] = lo;
}

// ---------------------------------------------------------------------------
// Tensor product via bf16x3 mma.sync, prepacked weights via cp.async.
// CTA: 64 batch rows x 128 w x 4 outputs; 16 warps = 4 outs x 4 row-quads.
// smem: bufw[2][8 part][8 kp][132] words (part = plane*2 + hilo).
// ---------------------------------------------------------------------------
template <int M>
__global__ __launch_bounds__(512, 1)
void tp_mma_kernel(const float* __restrict__ s1, const float* __restrict__ v1,
                   const float* __restrict__ s2, const float* __restrict__ v2,
                   const uint32_t* __restrict__ wp,   // 4 planes, stride M*M*128
                   float* __restrict__ ts, float* __restrict__ tv, float cscale) {
    extern __shared__ uint32_t dsm[];                 // 2 * 8448 words
    constexpr int PS = M * M * 128;                   // plane stride (words)
    const uint32_t smem_base = smem_u32(dsm);

    const int tid  = threadIdx.x;
    const int wid  = tid >> 5, lane = tid & 31;
    const int out  = wid & 3;
    const int q    = wid >> 2;
    const int g    = lane >> 2, t4 = lane & 3;
    const int bb   = blockIdx.x * 64;
    const int gb0  = bb + q * 16 + g;
    const int gb1  = gb0 + 8;

    // copy role
    const int cplane = tid >> 7;           // 0..3 weight plane
    const int crem   = tid & 127;
    const uint32_t* gw = wp + (size_t)cplane * PS;

    // part bases for this warp's two streams
    const int pa_hi = (out == 0) ? 0 : 4;  // ss / sv
    const int pb_hi = (out == 0) ? 2 : 6;  // vv / vs

    float acc[16][4];
#pragma unroll
    for (int nt = 0; nt < 16; ++nt)
#pragma unroll
        for (int j = 0; j < 4; ++j) acc[nt][j] = 0.f;

    const float* s1r0 = s1 + (size_t)gb0 * M;
    const float* s1r1 = s1 + (size_t)gb1 * M;
    const float* v1r0[3], *v1r1[3];
    const float* s2r0 = s2 + (size_t)gb0 * M;
    const float* s2r1 = s2 + (size_t)gb1 * M;
    const float* v2r0[3], *v2r1[3];
#pragma unroll
    for (int i = 0; i < 3; ++i) {
        v1r0[i] = v1 + (size_t)i * PLANE + (size_t)gb0 * M;
        v1r1[i] = v1 + (size_t)i * PLANE + (size_t)gb1 * M;
        v2r0[i] = v2 + (size_t)i * PLANE + (size_t)gb0 * M;
        v2r1[i] = v2 + (size_t)i * PLANE + (size_t)gb1 * M;
    }

    auto docopy = [&](int blk, int b) {
        const uint32_t* src = gw + (size_t)blk * 2048;
        const uint32_t sb0 = smem_base + (uint32_t)(b * 8448) * 4;
#pragma unroll
        for (int i = 0; i < 4; ++i) {
            int sg = crem + 128 * i;                      // 0..511
            int hilo = sg >> 8, kp = (sg >> 5) & 7, col = (sg & 31) * 4;
            uint32_t saddr = sb0 + (uint32_t)((((cplane * 2 + hilo) * 8 + kp) * 132 + col) * 4);
            CP_ASYNC16(saddr, src + (size_t)sg * 4);
        }
    };

    for (int vw = 0; vw < M / 16; ++vw) {
        const int v0w = vw * 16;
        const int blk0 = vw * M;

        docopy(blk0, 0);
        CP_COMMIT();

        for (int u = 0; u < M; ++u) {
            const int cur = u & 1;
            if (u + 1 < M) {
                docopy(blk0 + u + 1, cur ^ 1);
                CP_COMMIT();
                CP_WAIT1();
            } else {
                CP_WAIT0();
            }
            __syncthreads();

            // ---- a1, a2 operands (L1-resident gmem) ----
            float s1a[2], v1a[3][2];
            s1a[0] = __ldg(s1r0 + u);
            s1a[1] = __ldg(s1r1 + u);
#pragma unroll
            for (int i = 0; i < 3; ++i) {
                v1a[i][0] = __ldg(v1r0[i] + u);
                v1a[i][1] = __ldg(v1r1[i] + u);
            }
            const int ca = v0w + 2 * t4, cb = ca + 8;
            float s2v[2][4], v2v[3][2][4];
            {
                float2 A, B;
                A = __ldg((const float2*)(s2r0 + ca)); B = __ldg((const float2*)(s2r0 + cb));
                s2v[0][0]=A.x; s2v[0][1]=A.y; s2v[0][2]=B.x; s2v[0][3]=B.y;
                A = __ldg((const float2*)(s2r1 + ca)); B = __ldg((const float2*)(s2r1 + cb));
                s2v[1][0]=A.x; s2v[1][1]=A.y; s2v[1][2]=B.x; s2v[1][3]=B.y;
#pragma unroll
                for (int i = 0; i < 3; ++i) {
                    A = __ldg((const float2*)(v2r0[i] + ca)); B = __ldg((const float2*)(v2r0[i] + cb));
                    v2v[i][0][0]=A.x; v2v[i][0][1]=A.y; v2v[i][0][2]=B.x; v2v[i][0][3]=B.y;
                    A = __ldg((const float2*)(v2r1[i] + ca)); B = __ldg((const float2*)(v2r1[i] + cb));
                    v2v[i][1][0]=A.x; v2v[i][1][1]=A.y; v2v[i][1][2]=B.x; v2v[i][1][3]=B.y;
                }
            }

            // ---- products for both streams (a2 dead afterwards) ----
            float pav[2][4], pbv[2][4];
            if (out == 0) {
#pragma unroll
                for (int r = 0; r < 2; ++r)
#pragma unroll
                    for (int j = 0; j < 4; ++j) {
                        pav[r][j] = s1a[r] * s2v[r][j];
                        pbv[r][j] = INV_SQRT3 * (v1a[0][r] * v2v[0][r][j] +
                                                 v1a[1][r] * v2v[1][r][j] +
                                                 v1a[2][r] * v2v[2][r][j]);
                    }
            } else {
                const int i = out - 1;
#pragma unroll
                for (int r = 0; r < 2; ++r)
#pragma unroll
                    for (int j = 0; j < 4; ++j) {
                        pav[r][j] = s1a[r] * v2v[i][r][j];
                        pbv[r][j] = v1a[i][r] * s2v[r][j];
                    }
            }

            const uint32_t* bufb = dsm + cur * 8448;
            const uint32_t* bh0p = bufb + (pa_hi * 8 + t4) * 132 + g * 16;
            const uint32_t* bh1p = bufb + (pa_hi * 8 + t4 + 4) * 132 + g * 16;

            // ---- stream A: hi*hi + lo*hi + hi*lo ----
            {
                uint32_t fh[4], fl[4];
                split_pack(pav[0][0], pav[0][1], fh[0], fl[0]);
                split_pack(pav[1][0], pav[1][1], fh[1], fl[1]);
                split_pack(pav[0][2], pav[0][3], fh[2], fl[2]);
                split_pack(pav[1][2], pav[1][3], fh[3], fl[3]);
#pragma unroll
                for (int q4 = 0; q4 < 4; ++q4) {
                    uint4 h0 = *(const uint4*)(bh0p + q4 * 4);
                    uint4 h1 = *(const uint4*)(bh1p + q4 * 4);
                    uint4 l0 = *(const uint4*)(bh0p + 8 * 132 + q4 * 4);
                    uint4 l1 = *(const uint4*)(bh1p + 8 * 132 + q4 * 4);
                    uint32_t h0a[4] = {h0.x, h0.y, h0.z, h0.w};
                    uint32_t h1a[4] = {h1.x, h1.y, h1.z, h1.w};
                    uint32_t l0a[4] = {l0.x, l0.y, l0.z, l0.w};
                    uint32_t l1a[4] = {l1.x, l1.y, l1.z, l1.w};
#pragma unroll
                    for (int j = 0; j < 4; ++j) {
                        float* d = acc[q4 * 4 + j];
                        MMA_BF16(d, fh[0], fh[1], fh[2], fh[3], h0a[j], h1a[j]);
                        MMA_BF16(d, fl[0], fl[1], fl[2], fl[3], h0a[j], h1a[j]);
                        MMA_BF16(d, fh[0], fh[1], fh[2], fh[3], l0a[j], l1a[j]);
                    }
                }
            }
            // ---- stream B ----
            {
                const uint32_t* ch0p = bufb + (pb_hi * 8 + t4) * 132 + g * 16;
                const uint32_t* ch1p = bufb + (pb_hi * 8 + t4 + 4) * 132 + g * 16;
                uint32_t fh[4], fl[4];
                split_pack(pbv[0][0], pbv[0][1], fh[0], fl[0]);
                split_pack(pbv[1][0], pbv[1][1], fh[1], fl[1]);
                split_pack(pbv[0][2], pbv[0][3], fh[2], fl[2]);
                split_pack(pbv[1][2], pbv[1][3], fh[3], fl[3]);
#pragma unroll
                for (int q4 = 0; q4 < 4; ++q4) {
                    uint4 h0 = *(const uint4*)(ch0p + q4 * 4);
                    uint4 h1 = *(const uint4*)(ch1p + q4 * 4);
                    uint4 l0 = *(const uint4*)(ch0p + 8 * 132 + q4 * 4);
                    uint4 l1 = *(const uint4*)(ch1p + 8 * 132 + q4 * 4);
                    uint32_t h0a[4] = {h0.x, h0.y, h0.z, h0.w};
                    uint32_t h1a[4] = {h1.x, h1.y, h1.z, h1.w};
                    uint32_t l0a[4] = {l0.x, l0.y, l0.z, l0.w};
                    uint32_t l1a[4] = {l1.x, l1.y, l1.z, l1.w};
#pragma unroll
                    for (int j = 0; j < 4; ++j) {
                        float* d = acc[q4 * 4 + j];
                        MMA_BF16(d, fh[0], fh[1], fh[2], fh[3], h0a[j], h1a[j]);
                        MMA_BF16(d, fl[0], fl[1], fl[2], fl[3], h0a[j], h1a[j]);
                        MMA_BF16(d, fh[0], fh[1], fh[2], fh[3], l0a[j], l1a[j]);
                    }
                }
            }
            __syncthreads();   // consumers done before next overwrite
        }
    }

    // epilogue: n = nt*8 + g, thread cols 2*t4, 2*t4+1 within n-tile
    float* op = (out == 0) ? ts : tv + (size_t)(out - 1) * PLANE;
#pragma unroll
    for (int nt = 0; nt < 16; ++nt) {
        const int col = nt * 8 + 2 * t4;
        *(float2*)(op + (size_t)gb0 * 128 + col) =
            make_float2(cscale * acc[nt][0], cscale * acc[nt][1]);
        *(float2*)(op + (size_t)gb1 * 128 + col) =
            make_float2(cscale * acc[nt][2], cscale * acc[nt][3]);
    }
}

// ---------------------------------------------------------------------------
// split / pack / gemm / gate
// ---------------------------------------------------------------------------
__global__ void split_kernel(const float* __restrict__ x,
                             float* __restrict__ s, float* __restrict__ v) {
    int i = blockIdx.x * 256 + threadIdx.x;
    if (i >= BATCH * 64) return;
    int b = i >> 6, u = i & 63;
    const float* xr = x + b * 256;
    s[i] = xr[u];
    v[0 * PLANE + i] = xr[64 + 3 * u + 0];
    v[1 * PLANE + i] = xr[64 + 3 * u + 1];
    v[2 * PLANE + i] = xr[64 + 3 * u + 2];
}

__global__ void pack_kernel(const float* __restrict__ s,
                            const float* __restrict__ v,
                            float* __restrict__ out) {
    int i = blockIdx.x * 256 + threadIdx.x;
    if (i >= BATCH * 64) return;
    int b = i >> 6, u = i & 63;
    float* orow = out + b * 256;
    orow[u] = s[i];
    orow[64 + 3 * u + 0] = v[0 * PLANE + i];
    orow[64 + 3 * u + 1] = v[1 * PLANE + i];
    orow[64 + 3 * u + 2] = v[2 * PLANE + i];
}

// 32-row tiles for occupancy (grid = 256 * planes)
template <int NC>
__global__ __launch_bounds__(256)
void gemm_kernel(const float* __restrict__ X, const float* __restrict__ Wm,
                 float* __restrict__ Y, int K, float scale) {
    constexpr int N = 32 * NC;
    X += (size_t)blockIdx.y * PLANE;
    Y += (size_t)blockIdx.y * PLANE;
    __shared__ float Xs[32][33];
    __shared__ float Ws[32][N + 1];
    const int tx = threadIdx.x, ty = threadIdx.y;
    const int tid = ty * 32 + tx;
    const int row0 = blockIdx.x * 32;

    float acc[4][NC];
#pragma unroll
    for (int r = 0; r < 4; ++r)
#pragma unroll
        for (int j = 0; j < NC; ++j) acc[r][j] = 0.f;

    for (int k0 = 0; k0 < K; k0 += 32) {
#pragma unroll
        for (int e = tid; e < 32 * 32; e += 256) {
            int r = e >> 5, kk = e & 31;
            Xs[r][kk] = X[(size_t)(row0 + r) * K + k0 + kk];
        }
        for (int e = tid; e < 32 * N; e += 256) {
            int kk = e / N, n = e - kk * N;
            Ws[kk][n] = Wm[(size_t)(k0 + kk) * N + n];
        }
        __syncthreads();
#pragma unroll 8
        for (int kk = 0; kk < 32; ++kk) {
            float wv[NC];
#pragma unroll
            for (int j = 0; j < NC; ++j) wv[j] = Ws[kk][tx * NC + j];
#pragma unroll
            for (int r = 0; r < 4; ++r) {
                float xv = Xs[ty * 4 + r][kk];
#pragma unroll
                for (int j = 0; j < NC; ++j) acc[r][j] += xv * wv[j];
            }
        }
        __syncthreads();
    }
#pragma unroll
    for (int r = 0; r < 4; ++r)
#pragma unroll
        for (int j = 0; j < NC; ++j)
            Y[(size_t)(row0 + ty * 4 + r) * N + tx * NC + j] = scale * acc[r][j];
}

__global__ void gate_kernel(const float* __restrict__ sl, const float* __restrict__ g,
                            const float* __restrict__ vl,
                            float* __restrict__ gs, float* __restrict__ gv) {
    int i = blockIdx.x * 256 + threadIdx.x;
    if (i >= BATCH * 128) return;
    gs[i] = GAIN * tanhf(sl[i]);
    float t = GAIN * tanhf(g[i]);
    gv[0 * PLANE + i] = t * vl[0 * PLANE + i];
    gv[1 * PLANE + i] = t * vl[1 * PLANE + i];
    gv[2 * PLANE + i] = t * vl[2 * PLANE + i];
}

// ---------------------------------------------------------------------------
// Host orchestration
// ---------------------------------------------------------------------------
static inline void run_gemm(const float* X, const float* W, float* Y,
                            int K, int N, float scale, int planes) {
    dim3 blk(32, 8), grd(BATCH / 32, planes);
    if (N == 64) gemm_kernel<2><<<grd, blk>>>(X, W, Y, K, scale);
    else         gemm_kernel<4><<<grd, blk>>>(X, W, Y, K, scale);
}

extern "C" void kernel_launch(void* const* d_in, const int* in_sizes, int n_in,
                              void* d_out, int out_size) {
    const float* in[29];
    for (int i = 0; i < 29; ++i) in[i] = (const float*)d_in[i];
    float* out = (float*)d_out;

    float *s, *v, *s1, *v1, *s2, *v2, *ts, *tv;
    uint32_t *wp1, *wp2;
    cudaGetSymbolAddress((void**)&s,  g_s);
    cudaGetSymbolAddress((void**)&v,  g_v);
    cudaGetSymbolAddress((void**)&s1, g_s1);
    cudaGetSymbolAddress((void**)&v1, g_v1);
    cudaGetSymbolAddress((void**)&s2, g_s2);
    cudaGetSymbolAddress((void**)&v2, g_v2);
    cudaGetSymbolAddress((void**)&ts, g_ts);
    cudaGetSymbolAddress((void**)&tv, g_tv);
    cudaGetSymbolAddress((void**)&wp1, g_wp1);
    cudaGetSymbolAddress((void**)&wp2, g_wp2);

    const int TP_SMEM = 2 * 8448 * 4;   // 67584 bytes
    cudaFuncSetAttribute(tp_mma_kernel<64>,
                         cudaFuncAttributeMaxDynamicSharedMemorySize, TP_SMEM);
    cudaFuncSetAttribute(tp_mma_kernel<128>,
                         cudaFuncAttributeMaxDynamicSharedMemorySize, TP_SMEM);

    const float c64  = 0.125f;
    const float c128 = 0.08838834764831845f;
    const float ctp1 = 1.0f / (64.0f  * 1.4142135623730951f);
    const float ctp2 = 1.0f / (128.0f * 1.4142135623730951f);

    // ---- weight prepass (deterministic, every call) ----
    {
        const int t1 = (64 * 64 / 2) * 128;     // per block1 plane
        const int t2 = (128 * 128 / 2) * 128;   // per block2 plane
        for (int p = 0; p < 4; ++p)
            pack_weights_kernel<<<(t1 + 255) / 256, 256>>>(in[5 + p],  wp1 + (size_t)p * (64 * 64 * 128), 64);
        for (int p = 0; p < 4; ++p)
            pack_weights_kernel<<<(t2 + 255) / 256, 256>>>(in[18 + p], wp2 + (size_t)p * (128 * 128 * 128), 128);
    }

    split_kernel<<<BATCH * 64 / 256, 256>>>(in[0], s, v);

    // ---------------- block 1 (m = 64) ----------------
    run_gemm(s, in[1], s1, 64, 64, c64, 1);
    run_gemm(v, in[2], v1, 64, 64, c64, 3);
    run_gemm(s, in[3], s2, 64, 64, c64, 1);
    run_gemm(v, in[4], v2, 64, 64, c64, 3);

    tp_mma_kernel<64><<<BATCH / 64, 512, TP_SMEM>>>(
        s1, v1, s2, v2, wp1, ts, tv, ctp1);

    run_gemm(ts, in[9],  s1, 128, 128, c128, 1);
    run_gemm(ts, in[10], s2, 128, 128, c128, 1);
    run_gemm(tv, in[11], v1, 128, 128, c128, 3);
    gate_kernel<<<BATCH * 128 / 256, 256>>>(s1, s2, v1, ts, tv);

    run_gemm(ts, in[12], s, 128, 128, c128, 1);
    run_gemm(tv, in[13], v, 128, 128, c128, 3);

    // ---------------- block 2 (m = 128) ----------------
    run_gemm(s, in[14], s1, 128, 128, c128, 1);
    run_gemm(v, in[15], v1, 128, 128, c128, 3);
    run_gemm(s, in[16], s2, 128, 128, c128, 1);
    run_gemm(v, in[17], v2, 128, 128, c128, 3);

    tp_mma_kernel<128><<<BATCH / 64, 512, TP_SMEM>>>(
        s1, v1, s2, v2, wp2, ts, tv, ctp2);

    run_gemm(ts, in[22], s1, 128, 128, c128, 1);
    run_gemm(ts, in[23], s2, 128, 128, c128, 1);
    run_gemm(tv, in[24], v1, 128, 128, c128, 3);
    gate_kernel<<<BATCH * 128 / 256, 256>>>(s1, s2, v1, ts, tv);

    run_gemm(ts, in[25], s, 128, 128, c128, 1);
    run_gemm(tv, in[26], v, 128, 128, c128, 3);

    // ---------------- final linear + pack ----------------
    run_gemm(s, in[27], s1, 128, 64, c128, 1);
    run_gemm(v, in[28], v1, 128, 64, c128, 3);

    pack_kernel<<<BATCH * 64 / 256, 256>>>(s1, v1, out);
}